// round 6
// baseline (speedup 1.0000x reference)
#include <cuda_runtime.h>
#include <cstdint>

#define B_ 2
#define S_ 2048
#define D_ 4096
#define NQKV 12288
#define MROWS 4096

// ---------------- scratch ----------------------------------------------------
__device__ float g_WqkvT[(size_t)NQKV * D_];
__device__ float g_qkv  [(size_t)MROWS * NQKV];
__device__ float g_WoutT[(size_t)D_ * D_];
__device__ float g_ctx  [(size_t)MROWS * D_];
__device__ float g_hs32 [(size_t)MROWS * D_];

__device__ __forceinline__ uint32_t smem_u32(const void* p) {
    uint32_t a;
    asm("{ .reg .u64 t; cvta.to.shared.u64 t, %1; cvt.u32.u64 %0, t; }" : "=r"(a) : "l"(p));
    return a;
}
__device__ __forceinline__ float tf32f(float x) {
    uint32_t r; asm("cvt.rna.tf32.f32 %0, %1;" : "=r"(r) : "f"(x));
    return __uint_as_float(r);
}
__device__ __forceinline__ void ldsm4(uint32_t& r0, uint32_t& r1, uint32_t& r2,
                                      uint32_t& r3, uint32_t addr) {
    asm volatile("ldmatrix.sync.aligned.m8n8.x4.shared.b16 {%0,%1,%2,%3}, [%4];"
                 : "=r"(r0), "=r"(r1), "=r"(r2), "=r"(r3) : "r"(addr));
}
#define CPA16(dst, src) \
    asm volatile("cp.async.cg.shared.global [%0], [%1], 16;" :: "r"(dst), "l"(src))
#define MMA8(d, a, b0_, b1_) \
    asm volatile("mma.sync.aligned.m16n8k8.row.col.f32.tf32.tf32.f32 " \
                 "{%0,%1,%2,%3}, {%4,%5,%6,%7}, {%8,%9}, {%0,%1,%2,%3};" \
                 : "+f"(d[0]), "+f"(d[1]), "+f"(d[2]), "+f"(d[3]) \
                 : "r"(a[0]), "r"(a[1]), "r"(a[2]), "r"(a[3]), "r"(b0_), "r"(b1_))

// ---------------- GPTQ 4-bit dequant -> W^T [N,K], tf32-rounded -------------
__global__ void dequant_t_kernel(const int* __restrict__ qw, const int* __restrict__ qz,
                                 const float* __restrict__ sc, float* __restrict__ Wt, int N) {
    size_t idx = (size_t)blockIdx.x * blockDim.x + threadIdx.x;
    if (idx >= (size_t)(D_ / 8) * N) return;
    int n = (int)(idx % N);
    int r = (int)(idx / N);
    int g = r >> 4;
    unsigned w = (unsigned)qw[(size_t)r * N + n];
    unsigned z = (unsigned)qz[(size_t)g * (N / 8) + (n >> 3)];
    int zp = (int)((z >> ((n & 7) * 4)) & 15u) + 1;
    float s = sc[(size_t)g * N + n];
    float v[8];
#pragma unroll
    for (int j = 0; j < 8; j++)
        v[j] = tf32f(s * (float)((int)((w >> (j * 4)) & 15u) - zp));
    float* dst = Wt + (size_t)n * D_ + (size_t)r * 8;
    *(float4*)dst       = make_float4(v[0], v[1], v[2], v[3]);
    *(float4*)(dst + 4) = make_float4(v[4], v[5], v[6], v[7]);
}

__global__ void tf32_copy_kernel(const float4* __restrict__ src, float4* __restrict__ dst) {
    size_t i = (size_t)blockIdx.x * blockDim.x + threadIdx.x;
    float4 v = src[i];
    dst[i] = make_float4(tf32f(v.x), tf32f(v.y), tf32f(v.z), tf32f(v.w));
}

// ---------------- tf32 mma GEMM v2: C[M,N] = A[M,K] @ Bt[N,K]^T --------------
// 256 thr, 8 warps (2Mx4N), block 128x256, warp 64x64, BK=32, 3-stage cp.async.
#define STG 49152
__global__ __launch_bounds__(256, 1) void tf32_gemm(const float* __restrict__ A,
                                                    const float* __restrict__ Bt,
                                                    float* __restrict__ C, int N) {
    extern __shared__ char smraw[];
    const uint32_t sb = smem_u32(smraw);
    const int tid = threadIdx.x;
    const int L = tid & 31;
    const int wid = tid >> 5;
    const int wm = wid >> 2, wn = wid & 3;

    const float* Ag = A + (size_t)(blockIdx.y * 128) * 4096;
    const float* Bg = Bt + (size_t)(blockIdx.x * 256) * 4096;

    auto stage_load = [&](int kc, int st) {
        uint32_t sA = sb + st * STG;
        uint32_t sB = sA + 16384;
        const float* Ap = Ag + kc * 32;
        const float* Bp = Bg + kc * 32;
#pragma unroll
        for (int i = 0; i < 4; i++) {
            int f = tid + i * 256, r = f >> 3, c = f & 7;
            CPA16(sA + r * 128 + ((c * 16) ^ ((r & 7) << 4)), Ap + (size_t)r * 4096 + c * 4);
        }
#pragma unroll
        for (int i = 0; i < 8; i++) {
            int f = tid + i * 256, r = f >> 3, c = f & 7;
            CPA16(sB + r * 128 + ((c * 16) ^ ((r & 7) << 4)), Bp + (size_t)r * 4096 + c * 4);
        }
        asm volatile("cp.async.commit_group;" ::: "memory");
    };

    float acc[4][8][4];
#pragma unroll
    for (int mt = 0; mt < 4; mt++)
#pragma unroll
        for (int nt = 0; nt < 8; nt++)
#pragma unroll
            for (int j = 0; j < 4; j++) acc[mt][nt][j] = 0.f;

    stage_load(0, 0);
    stage_load(1, 1);

#pragma unroll 1
    for (int i = 0; i < 128; i++) {
        if (i < 127) asm volatile("cp.async.wait_group 1;" ::: "memory");
        else         asm volatile("cp.async.wait_group 0;" ::: "memory");
        __syncthreads();
        if (i + 2 < 128) stage_load(i + 2, (i + 2) % 3);
        uint32_t sA = sb + (i % 3) * STG;
        uint32_t sB = sA + 16384;
#pragma unroll
        for (int ks = 0; ks < 4; ks++) {
            uint32_t a[4][4];
#pragma unroll
            for (int mt = 0; mt < 4; mt++) {
                int row = wm * 64 + mt * 16 + (L & 15);
                ldsm4(a[mt][0], a[mt][1], a[mt][2], a[mt][3],
                      sA + row * 128 + (((2 * ks + (L >> 4)) * 16) ^ ((row & 7) << 4)));
            }
#pragma unroll
            for (int np = 0; np < 4; np++) {
                int n = wn * 64 + np * 16 + ((L & 7) | ((L & 16) >> 1));
                uint32_t b0, b1, b2, b3;
                ldsm4(b0, b1, b2, b3,
                      sB + n * 128 + (((2 * ks + ((L >> 3) & 1)) * 16) ^ ((n & 7) << 4)));
#pragma unroll
                for (int mt = 0; mt < 4; mt++) {
                    MMA8(acc[mt][2 * np], a[mt], b0, b1);
                    MMA8(acc[mt][2 * np + 1], a[mt], b2, b3);
                }
            }
        }
    }

    const int row0 = blockIdx.y * 128 + wm * 64 + (L >> 2);
    const int col0 = blockIdx.x * 256 + wn * 64 + 2 * (L & 3);
#pragma unroll
    for (int mt = 0; mt < 4; mt++)
#pragma unroll
        for (int nt = 0; nt < 8; nt++) {
            float* p = C + (size_t)(row0 + mt * 16) * N + col0 + nt * 8;
            *(float2*)p = make_float2(acc[mt][nt][0], acc[mt][nt][1]);
            *(float2*)(p + (size_t)8 * N) = make_float2(acc[mt][nt][2], acc[mt][nt][3]);
        }
}

// ---------------- RoPE -------------------------------------------------------
__global__ void rope_kernel(float* __restrict__ qkv) {
    int bs = blockIdx.x;
    int s = bs & (S_ - 1);
    int h = threadIdx.x >> 5;
    int i = threadIdx.x & 31;
    float inv_freq = 1.0f / powf(10000.0f, (float)(2 * i) / 64.0f);
    float ang = (float)s * inv_freq;
    float sn = sinf(ang), cs = cosf(ang);
    size_t base = (size_t)bs * NQKV + (size_t)h * 256 + 2 * i;
    float* q = qkv + base;
    float* k = qkv + base + D_;
    float q0 = q[0], q1 = q[1];
    q[0] = q0 * cs - q1 * sn;
    q[1] = q1 * cs + q0 * sn;
    float k0 = k[0], k1 = k[1];
    k[0] = k0 * cs - k1 * sn;
    k[1] = k1 * cs + k0 * sn;
}

// ---------------- causal flash attention (fp32, unchanged) -------------------
#define SWZ(d, c) ((d) ^ ((c) << 2))
__global__ __launch_bounds__(256) void attn_kernel(const float* __restrict__ qkv,
                                                   float* __restrict__ ctx) {
    extern __shared__ float smf[];
    float* Ks = smf;
    float* Vs = smf + 32 * 256;
    const int tid = threadIdx.x;
    const int ql = tid >> 3;
    const int c = tid & 7;
    const int b = blockIdx.y >> 4, h = blockIdx.y & 15;
    const int qg = blockIdx.x * 32 + ql;
    const float* base = qkv + (size_t)b * S_ * NQKV;

    float qreg[32], o[32], s[32];
    const float* qrow = base + (size_t)qg * NQKV + h * 256 + c * 32;
#pragma unroll
    for (int t = 0; t < 8; t++) {
        float4 v = *(const float4*)(qrow + 4 * t);
        qreg[4 * t] = v.x; qreg[4 * t + 1] = v.y;
        qreg[4 * t + 2] = v.z; qreg[4 * t + 3] = v.w;
    }
#pragma unroll
    for (int j = 0; j < 32; j++) o[j] = 0.f;
    float m = -1e30f, l = 0.f;

    const int nt = blockIdx.x + 1;
    for (int kt = 0; kt < nt; kt++) {
        const int k0 = kt * 32;
        __syncthreads();
#pragma unroll
        for (int i = 0; i < 8; i++) {
            int f = tid + i * 256;
            int r = f >> 6;
            int cc = (f & 63) * 4;
            int pc = cc ^ ((((unsigned)cc >> 5) & 7) << 2);
            const float* kg = base + (size_t)(k0 + r) * NQKV + D_ + h * 256 + cc;
            *(float4*)&Ks[r * 256 + pc] = *(const float4*)kg;
            *(float4*)&Vs[r * 256 + pc] = *(const float4*)(kg + D_);
        }
        __syncthreads();
#pragma unroll
        for (int kk = 0; kk < 32; kk++) s[kk] = 0.f;
#pragma unroll
        for (int t = 0; t < 8; t++) {
            const int dph = SWZ(c * 32 + t * 4, c);
            float a0 = qreg[4 * t], a1 = qreg[4 * t + 1];
            float a2 = qreg[4 * t + 2], a3 = qreg[4 * t + 3];
#pragma unroll
            for (int kk = 0; kk < 32; kk++) {
                float4 kv = *(const float4*)&Ks[kk * 256 + dph];
                s[kk] += a0 * kv.x + a1 * kv.y + a2 * kv.z + a3 * kv.w;
            }
        }
#pragma unroll
        for (int kk = 0; kk < 32; kk++) {
            float v = s[kk];
            v += __shfl_xor_sync(0xffffffffu, v, 1);
            v += __shfl_xor_sync(0xffffffffu, v, 2);
            v += __shfl_xor_sync(0xffffffffu, v, 4);
            s[kk] = v * 0.0625f;
        }
        if (kt == nt - 1) {
#pragma unroll
            for (int kk = 0; kk < 32; kk++)
                if (k0 + kk > qg) s[kk] = -1e30f;
        }
        float mt = m;
#pragma unroll
        for (int kk = 0; kk < 32; kk++) mt = fmaxf(mt, s[kk]);
        float resc = __expf(m - mt);
        l *= resc;
#pragma unroll
        for (int j = 0; j < 32; j++) o[j] *= resc;
#pragma unroll
        for (int kk = 0; kk < 32; kk++) {
            s[kk] = __expf(s[kk] - mt);
            l += s[kk];
        }
        m = mt;
#pragma unroll
        for (int t = 0; t < 8; t++) {
            const int dph = SWZ(c * 32 + t * 4, c);
            float a0 = 0.f, a1 = 0.f, a2 = 0.f, a3 = 0.f;
#pragma unroll
            for (int kk = 0; kk < 32; kk++) {
                float4 vv = *(const float4*)&Vs[kk * 256 + dph];
                a0 += s[kk] * vv.x; a1 += s[kk] * vv.y;
                a2 += s[kk] * vv.z; a3 += s[kk] * vv.w;
            }
            o[4 * t] += a0; o[4 * t + 1] += a1;
            o[4 * t + 2] += a2; o[4 * t + 3] += a3;
        }
    }
    float invl = 1.f / l;
    float* outp = ctx + (size_t)(b * S_ + qg) * D_ + h * 256 + c * 32;
#pragma unroll
    for (int t = 0; t < 8; t++) {
        float4 v = make_float4(tf32f(o[4 * t] * invl), tf32f(o[4 * t + 1] * invl),
                               tf32f(o[4 * t + 2] * invl), tf32f(o[4 * t + 3] * invl));
        *(float4*)(outp + 4 * t) = v;
    }
}

// ---------------- launch ------------------------------------------------------
extern "C" void kernel_launch(void* const* d_in, const int* in_sizes, int n_in,
                              void* d_out, int out_size) {
    const float* hs     = (const float*)d_in[0];
    const int*   qw_qkv = (const int*)  d_in[1];
    const int*   qz_qkv = (const int*)  d_in[2];
    const float* sc_qkv = (const float*)d_in[3];
    const int*   qw_out = (const int*)  d_in[4];
    const int*   qz_out = (const int*)  d_in[5];
    const float* sc_out = (const float*)d_in[6];
    float* out = (float*)d_out;

    float *WqkvT, *qkv, *WoutT, *ctx, *hs32;
    cudaGetSymbolAddress((void**)&WqkvT, g_WqkvT);
    cudaGetSymbolAddress((void**)&qkv,   g_qkv);
    cudaGetSymbolAddress((void**)&WoutT, g_WoutT);
    cudaGetSymbolAddress((void**)&ctx,   g_ctx);
    cudaGetSymbolAddress((void**)&hs32,  g_hs32);

    cudaFuncSetAttribute(tf32_gemm,
                         cudaFuncAttributeMaxDynamicSharedMemorySize, 3 * STG);
    cudaFuncSetAttribute(attn_kernel,
                         cudaFuncAttributeMaxDynamicSharedMemorySize, 65536);

    dequant_t_kernel<<<(D_ / 8) * (NQKV / 256), 256>>>(qw_qkv, qz_qkv, sc_qkv, WqkvT, NQKV);
    dequant_t_kernel<<<(D_ / 8) * (D_   / 256), 256>>>(qw_out, qz_out, sc_out, WoutT, D_);
    tf32_copy_kernel<<<(MROWS * (D_ / 4)) / 256, 256>>>((const float4*)hs, (float4*)hs32);

    dim3 g1(NQKV / 256, MROWS / 128);
    tf32_gemm<<<g1, 256, 3 * STG>>>(hs32, WqkvT, qkv, NQKV);

    rope_kernel<<<B_ * S_, 512>>>(qkv);

    dim3 g2(S_ / 32, 32);
    attn_kernel<<<g2, 256, 65536>>>(qkv, ctx);

    dim3 g3(D_ / 256, MROWS / 128);
    tf32_gemm<<<g3, 256, 3 * STG>>>(ctx, WoutT, out, D_);
}

// round 7
// speedup vs baseline: 1.8555x; 1.8555x over previous
#include <cuda_runtime.h>
#include <cstdint>

#define B_ 2
#define S_ 2048
#define D_ 4096
#define NQKV 12288
#define MROWS 4096

// ---------------- scratch ----------------------------------------------------
__device__ float g_WqkvT[(size_t)NQKV * D_];
__device__ float g_qkv  [(size_t)MROWS * NQKV];
__device__ float g_WoutT[(size_t)D_ * D_];
__device__ float g_ctx  [(size_t)MROWS * D_];
__device__ float g_hs32 [(size_t)MROWS * D_];

__device__ __forceinline__ uint32_t smem_u32(const void* p) {
    uint32_t a;
    asm("{ .reg .u64 t; cvta.to.shared.u64 t, %1; cvt.u32.u64 %0, t; }" : "=r"(a) : "l"(p));
    return a;
}
__device__ __forceinline__ float tf32f(float x) {
    uint32_t r; asm("cvt.rna.tf32.f32 %0, %1;" : "=r"(r) : "f"(x));
    return __uint_as_float(r);
}
__device__ __forceinline__ void ldsm4(uint32_t& r0, uint32_t& r1, uint32_t& r2,
                                      uint32_t& r3, uint32_t addr) {
    asm volatile("ldmatrix.sync.aligned.m8n8.x4.shared.b16 {%0,%1,%2,%3}, [%4];"
                 : "=r"(r0), "=r"(r1), "=r"(r2), "=r"(r3) : "r"(addr));
}
#define CPA16(dst, src) \
    asm volatile("cp.async.cg.shared.global [%0], [%1], 16;" :: "r"(dst), "l"(src))
#define MMA8(d, a, b0_, b1_) \
    asm volatile("mma.sync.aligned.m16n8k8.row.col.f32.tf32.tf32.f32 " \
                 "{%0,%1,%2,%3}, {%4,%5,%6,%7}, {%8,%9}, {%0,%1,%2,%3};" \
                 : "+f"(d[0]), "+f"(d[1]), "+f"(d[2]), "+f"(d[3]) \
                 : "r"(a[0]), "r"(a[1]), "r"(a[2]), "r"(a[3]), "r"(b0_), "r"(b1_))

// ---------------- GPTQ 4-bit dequant -> W^T [N,K], tf32-rounded -------------
__global__ void dequant_t_kernel(const int* __restrict__ qw, const int* __restrict__ qz,
                                 const float* __restrict__ sc, float* __restrict__ Wt, int N) {
    size_t idx = (size_t)blockIdx.x * blockDim.x + threadIdx.x;
    if (idx >= (size_t)(D_ / 8) * N) return;
    int n = (int)(idx % N);
    int r = (int)(idx / N);
    int g = r >> 4;
    unsigned w = (unsigned)qw[(size_t)r * N + n];
    unsigned z = (unsigned)qz[(size_t)g * (N / 8) + (n >> 3)];
    int zp = (int)((z >> ((n & 7) * 4)) & 15u) + 1;
    float s = sc[(size_t)g * N + n];
    float v[8];
#pragma unroll
    for (int j = 0; j < 8; j++)
        v[j] = tf32f(s * (float)((int)((w >> (j * 4)) & 15u) - zp));
    float* dst = Wt + (size_t)n * D_ + (size_t)r * 8;
    *(float4*)dst       = make_float4(v[0], v[1], v[2], v[3]);
    *(float4*)(dst + 4) = make_float4(v[4], v[5], v[6], v[7]);
}

__global__ void tf32_copy_kernel(const float4* __restrict__ src, float4* __restrict__ dst) {
    size_t i = (size_t)blockIdx.x * blockDim.x + threadIdx.x;
    float4 v = src[i];
    dst[i] = make_float4(tf32f(v.x), tf32f(v.y), tf32f(v.z), tf32f(v.w));
}
__global__ void tf32_inplace_kernel(float4* __restrict__ p) {
    size_t i = (size_t)blockIdx.x * blockDim.x + threadIdx.x;
    float4 v = p[i];
    p[i] = make_float4(tf32f(v.x), tf32f(v.y), tf32f(v.z), tf32f(v.w));
}

// ---------------- tf32 mma GEMM (unchanged from R6) --------------------------
#define STG 49152
__global__ __launch_bounds__(256, 1) void tf32_gemm(const float* __restrict__ A,
                                                    const float* __restrict__ Bt,
                                                    float* __restrict__ C, int N) {
    extern __shared__ char smraw[];
    const uint32_t sb = smem_u32(smraw);
    const int tid = threadIdx.x;
    const int L = tid & 31;
    const int wid = tid >> 5;
    const int wm = wid >> 2, wn = wid & 3;

    const float* Ag = A + (size_t)(blockIdx.y * 128) * 4096;
    const float* Bg = Bt + (size_t)(blockIdx.x * 256) * 4096;

    auto stage_load = [&](int kc, int st) {
        uint32_t sA = sb + st * STG;
        uint32_t sB = sA + 16384;
        const float* Ap = Ag + kc * 32;
        const float* Bp = Bg + kc * 32;
#pragma unroll
        for (int i = 0; i < 4; i++) {
            int f = tid + i * 256, r = f >> 3, c = f & 7;
            CPA16(sA + r * 128 + ((c * 16) ^ ((r & 7) << 4)), Ap + (size_t)r * 4096 + c * 4);
        }
#pragma unroll
        for (int i = 0; i < 8; i++) {
            int f = tid + i * 256, r = f >> 3, c = f & 7;
            CPA16(sB + r * 128 + ((c * 16) ^ ((r & 7) << 4)), Bp + (size_t)r * 4096 + c * 4);
        }
        asm volatile("cp.async.commit_group;" ::: "memory");
    };

    float acc[4][8][4];
#pragma unroll
    for (int mt = 0; mt < 4; mt++)
#pragma unroll
        for (int nt = 0; nt < 8; nt++)
#pragma unroll
            for (int j = 0; j < 4; j++) acc[mt][nt][j] = 0.f;

    stage_load(0, 0);
    stage_load(1, 1);

#pragma unroll 1
    for (int i = 0; i < 128; i++) {
        if (i < 127) asm volatile("cp.async.wait_group 1;" ::: "memory");
        else         asm volatile("cp.async.wait_group 0;" ::: "memory");
        __syncthreads();
        if (i + 2 < 128) stage_load(i + 2, (i + 2) % 3);
        uint32_t sA = sb + (i % 3) * STG;
        uint32_t sB = sA + 16384;
#pragma unroll
        for (int ks = 0; ks < 4; ks++) {
            uint32_t a[4][4];
#pragma unroll
            for (int mt = 0; mt < 4; mt++) {
                int row = wm * 64 + mt * 16 + (L & 15);
                ldsm4(a[mt][0], a[mt][1], a[mt][2], a[mt][3],
                      sA + row * 128 + (((2 * ks + (L >> 4)) * 16) ^ ((row & 7) << 4)));
            }
#pragma unroll
            for (int np = 0; np < 4; np++) {
                int n = wn * 64 + np * 16 + ((L & 7) | ((L & 16) >> 1));
                uint32_t b0, b1, b2, b3;
                ldsm4(b0, b1, b2, b3,
                      sB + n * 128 + (((2 * ks + ((L >> 3) & 1)) * 16) ^ ((n & 7) << 4)));
#pragma unroll
                for (int mt = 0; mt < 4; mt++) {
                    MMA8(acc[mt][2 * np], a[mt], b0, b1);
                    MMA8(acc[mt][2 * np + 1], a[mt], b2, b3);
                }
            }
        }
    }

    const int row0 = blockIdx.y * 128 + wm * 64 + (L >> 2);
    const int col0 = blockIdx.x * 256 + wn * 64 + 2 * (L & 3);
#pragma unroll
    for (int mt = 0; mt < 4; mt++)
#pragma unroll
        for (int nt = 0; nt < 8; nt++) {
            float* p = C + (size_t)(row0 + mt * 16) * N + col0 + nt * 8;
            *(float2*)p = make_float2(acc[mt][nt][0], acc[mt][nt][1]);
            *(float2*)(p + (size_t)8 * N) = make_float2(acc[mt][nt][2], acc[mt][nt][3]);
        }
}

// ---------------- RoPE -------------------------------------------------------
__global__ void rope_kernel(float* __restrict__ qkv) {
    int bs = blockIdx.x;
    int s = bs & (S_ - 1);
    int h = threadIdx.x >> 5;
    int i = threadIdx.x & 31;
    float inv_freq = 1.0f / powf(10000.0f, (float)(2 * i) / 64.0f);
    float ang = (float)s * inv_freq;
    float sn = sinf(ang), cs = cosf(ang);
    size_t base = (size_t)bs * NQKV + (size_t)h * 256 + 2 * i;
    float* q = qkv + base;
    float* k = qkv + base + D_;
    float q0 = q[0], q1 = q[1];
    q[0] = q0 * cs - q1 * sn;
    q[1] = q1 * cs + q0 * sn;
    float k0 = k[0], k1 = k[1];
    k[0] = k0 * cs - k1 * sn;
    k[1] = k1 * cs + k0 * sn;
}

// ---------------- tensor-core causal flash attention -------------------------
// 128 thr (4 warps x 16 q rows), 64-q blocks, 32-key tiles.
// SMEM: Q 64KB @0 | K 2x32KB @65536 | Vt 2x32KB @131072 | P 8KB @196608
#define ATT_SMEM 204800
__global__ __launch_bounds__(128, 1) void attn_mma(const float* __restrict__ qkv,
                                                   float* __restrict__ ctx) {
    extern __shared__ char smraw[];
    const uint32_t sb = smem_u32(smraw);
    const int tid = threadIdx.x, w = tid >> 5, L = tid & 31;
    const int qb = gridDim.x - 1 - blockIdx.x;        // big blocks first
    const int b = blockIdx.y >> 4, h = blockIdx.y & 15;
    const int qg0 = qb * 64;
    const float* base = qkv + (size_t)b * S_ * NQKV;
    const int nkt = 2 * qb + 2;

    // stage Q + K tile 0 via cp.async  (layout: row*8+chunk rows of 128B, swizzled)
#pragma unroll
    for (int i = 0; i < 32; i++) {
        int f = tid + i * 128, q = f >> 6, c4 = f & 63;
        CPA16(sb + (q * 8 + (c4 >> 3)) * 128 + (((c4 & 7) * 16) ^ ((q & 7) << 4)),
              base + (size_t)(qg0 + q) * NQKV + h * 256 + c4 * 4);
    }
#pragma unroll
    for (int i = 0; i < 16; i++) {
        int f = tid + i * 128, key = f >> 6, c4 = f & 63;
        CPA16(sb + 65536 + (key * 8 + (c4 >> 3)) * 128 + (((c4 & 7) * 16) ^ ((key & 7) << 4)),
              base + (size_t)key * NQKV + D_ + h * 256 + c4 * 4);
    }
    asm volatile("cp.async.commit_group;" ::: "memory");

    float O[32][4];
#pragma unroll
    for (int nt = 0; nt < 32; nt++)
#pragma unroll
        for (int j = 0; j < 4; j++) O[nt][j] = 0.f;
    float mlo = -1e30f, mhi = -1e30f, llo = 0.f, lhi = 0.f;

#pragma unroll 1
    for (int kt = 0; kt < nkt; kt++) {
        const int k0 = kt * 32, buf = kt & 1;
        const uint32_t Kb = sb + 65536 + buf * 32768;
        const uint32_t Vb = sb + 131072 + buf * 32768;

        // V batch1 LDG (thread: key=k0+L, d block 64w.., 8 float4)
        const float* vsrc = base + (size_t)(k0 + L) * NQKV + 2 * D_ + h * 256 + 64 * w;
        float4 vreg[8];
#pragma unroll
        for (int j = 0; j < 8; j++) vreg[j] = *(const float4*)(vsrc + 4 * j);

        asm volatile("cp.async.wait_group 0;" ::: "memory");
        __syncthreads();

        if (kt + 1 < nkt) {   // prefetch next K
            uint32_t Kn = sb + 65536 + (buf ^ 1) * 32768;
#pragma unroll
            for (int i = 0; i < 16; i++) {
                int f = tid + i * 128, key = f >> 6, c4 = f & 63;
                CPA16(Kn + (key * 8 + (c4 >> 3)) * 128 + (((c4 & 7) * 16) ^ ((key & 7) << 4)),
                      base + (size_t)(k0 + 32 + key) * NQKV + D_ + h * 256 + c4 * 4);
            }
            asm volatile("cp.async.commit_group;" ::: "memory");
        }

        float s[4][4];
#pragma unroll
        for (int nt = 0; nt < 4; nt++)
#pragma unroll
            for (int j = 0; j < 4; j++) s[nt][j] = 0.f;

        // S = Q K^T  (half 1: ks 0..15)
#pragma unroll
        for (int ks = 0; ks < 16; ks++) {
            uint32_t a[4];
            int row = 16 * w + (L & 15);
            ldsm4(a[0], a[1], a[2], a[3],
                  sb + (row * 8 + (ks >> 2)) * 128 +
                  (((2 * (ks & 3) + (L >> 4)) * 16) ^ ((L & 7) << 4)));
#pragma unroll
            for (int np = 0; np < 2; np++) {
                int n = np * 16 + ((L & 7) | ((L & 16) >> 1));
                uint32_t b0, b1, b2, b3;
                ldsm4(b0, b1, b2, b3,
                      Kb + (n * 8 + (ks >> 2)) * 128 +
                      (((2 * (ks & 3) + ((L >> 3) & 1)) * 16) ^ ((n & 7) << 4)));
                MMA8(s[2 * np], a, b0, b1);
                MMA8(s[2 * np + 1], a, b2, b3);
            }
        }
        // stash V batch1 (tf32-rounded, transposed), LDG batch2
#pragma unroll
        for (int j = 0; j < 8; j++) {
            int d0 = 64 * w + 4 * j;
            float vv[4] = {vreg[j].x, vreg[j].y, vreg[j].z, vreg[j].w};
#pragma unroll
            for (int e = 0; e < 4; e++) {
                int d = d0 + e;
                *(float*)(smraw + 131072 + buf * 32768 + d * 128 +
                          ((4 * L) ^ ((d & 7) << 4))) = vv[e];
            }
        }
#pragma unroll
        for (int j = 0; j < 8; j++) vreg[j] = *(const float4*)(vsrc + 32 + 4 * j);
        // S half 2: ks 16..31
#pragma unroll
        for (int ks = 16; ks < 32; ks++) {
            uint32_t a[4];
            int row = 16 * w + (L & 15);
            ldsm4(a[0], a[1], a[2], a[3],
                  sb + (row * 8 + (ks >> 2)) * 128 +
                  (((2 * (ks & 3) + (L >> 4)) * 16) ^ ((L & 7) << 4)));
#pragma unroll
            for (int np = 0; np < 2; np++) {
                int n = np * 16 + ((L & 7) | ((L & 16) >> 1));
                uint32_t b0, b1, b2, b3;
                ldsm4(b0, b1, b2, b3,
                      Kb + (n * 8 + (ks >> 2)) * 128 +
                      (((2 * (ks & 3) + ((L >> 3) & 1)) * 16) ^ ((n & 7) << 4)));
                MMA8(s[2 * np], a, b0, b1);
                MMA8(s[2 * np + 1], a, b2, b3);
            }
        }
#pragma unroll
        for (int j = 0; j < 8; j++) {
            int d0 = 64 * w + 32 + 4 * j;
            float vv[4] = {vreg[j].x, vreg[j].y, vreg[j].z, vreg[j].w};
#pragma unroll
            for (int e = 0; e < 4; e++) {
                int d = d0 + e;
                *(float*)(smraw + 131072 + buf * 32768 + d * 128 +
                          ((4 * L) ^ ((d & 7) << 4))) = vv[e];
            }
        }
        __syncthreads();   // Vt[buf] complete for all warps

        // ---- online softmax (two rows per lane) ----
#pragma unroll
        for (int nt = 0; nt < 4; nt++)
#pragma unroll
            for (int j = 0; j < 4; j++) s[nt][j] *= 0.0625f;
        if (k0 + 31 > qg0 + 16 * w) {
            int glo = qg0 + 16 * w + (L >> 2);
#pragma unroll
            for (int nt = 0; nt < 4; nt++) {
                int col = k0 + nt * 8 + 2 * (L & 3);
                if (col > glo)         s[nt][0] = -1e30f;
                if (col + 1 > glo)     s[nt][1] = -1e30f;
                if (col > glo + 8)     s[nt][2] = -1e30f;
                if (col + 1 > glo + 8) s[nt][3] = -1e30f;
            }
        }
        float tlo = -1e30f, thi = -1e30f;
#pragma unroll
        for (int nt = 0; nt < 4; nt++) {
            tlo = fmaxf(tlo, fmaxf(s[nt][0], s[nt][1]));
            thi = fmaxf(thi, fmaxf(s[nt][2], s[nt][3]));
        }
        tlo = fmaxf(tlo, __shfl_xor_sync(0xffffffffu, tlo, 1));
        tlo = fmaxf(tlo, __shfl_xor_sync(0xffffffffu, tlo, 2));
        thi = fmaxf(thi, __shfl_xor_sync(0xffffffffu, thi, 1));
        thi = fmaxf(thi, __shfl_xor_sync(0xffffffffu, thi, 2));
        float mnl = fmaxf(mlo, tlo), mnh = fmaxf(mhi, thi);
        float rl = __expf(mlo - mnl), rh = __expf(mhi - mnh);
        mlo = mnl; mhi = mnh;
#pragma unroll
        for (int nt = 0; nt < 32; nt++) {
            O[nt][0] *= rl; O[nt][1] *= rl; O[nt][2] *= rh; O[nt][3] *= rh;
        }
        float psl = 0.f, psh = 0.f;
        {
            int qlo = 16 * w + (L >> 2);
            uint32_t swz = ((qlo & 7) << 4);
#pragma unroll
            for (int nt = 0; nt < 4; nt++) {
                float p0 = tf32f(__expf(s[nt][0] - mnl));
                float p1 = tf32f(__expf(s[nt][1] - mnl));
                float p2 = tf32f(__expf(s[nt][2] - mnh));
                float p3 = tf32f(__expf(s[nt][3] - mnh));
                psl += p0 + p1; psh += p2 + p3;
                uint32_t off = (uint32_t)(nt * 32 + 8 * (L & 3));
                *(float2*)(smraw + 196608 + qlo * 128 + (off ^ swz)) = make_float2(p0, p1);
                *(float2*)(smraw + 196608 + (qlo + 8) * 128 + (off ^ swz)) = make_float2(p2, p3);
            }
        }
        psl += __shfl_xor_sync(0xffffffffu, psl, 1);
        psl += __shfl_xor_sync(0xffffffffu, psl, 2);
        psh += __shfl_xor_sync(0xffffffffu, psh, 1);
        psh += __shfl_xor_sync(0xffffffffu, psh, 2);
        llo = llo * rl + psl;
        lhi = lhi * rh + psh;
        __syncwarp();

        // ---- O += P @ V  (A=P[16][32], B=Vt[256][32]) ----
#pragma unroll
        for (int ks = 0; ks < 4; ks++) {
            uint32_t a[4];
            int row = 16 * w + (L & 15);
            ldsm4(a[0], a[1], a[2], a[3],
                  sb + 196608 + row * 128 + (((2 * ks + (L >> 4)) * 16) ^ ((L & 7) << 4)));
#pragma unroll
            for (int np = 0; np < 16; np++) {
                int d = np * 16 + ((L & 7) | ((L & 16) >> 1));
                uint32_t b0, b1, b2, b3;
                ldsm4(b0, b1, b2, b3,
                      Vb + d * 128 + (((2 * ks + ((L >> 3) & 1)) * 16) ^ ((d & 7) << 4)));
                MMA8(O[2 * np], a, b0, b1);
                MMA8(O[2 * np + 1], a, b2, b3);
            }
        }
        __syncwarp();
    }

    // ---- epilogue: normalize, tf32-round for next GEMM, store ----
    float il = 1.f / llo, ih = 1.f / lhi;
    float* cp = ctx + ((size_t)(b * S_ + qg0 + 16 * w + (L >> 2))) * D_ + h * 256 + 2 * (L & 3);
#pragma unroll
    for (int nt = 0; nt < 32; nt++) {
        *(float2*)(cp + nt * 8) =
            make_float2(tf32f(O[nt][0] * il), tf32f(O[nt][1] * il));
        *(float2*)(cp + (size_t)8 * D_ + nt * 8) =
            make_float2(tf32f(O[nt][2] * ih), tf32f(O[nt][3] * ih));
    }
}

// ---------------- launch ------------------------------------------------------
extern "C" void kernel_launch(void* const* d_in, const int* in_sizes, int n_in,
                              void* d_out, int out_size) {
    const float* hs     = (const float*)d_in[0];
    const int*   qw_qkv = (const int*)  d_in[1];
    const int*   qz_qkv = (const int*)  d_in[2];
    const float* sc_qkv = (const float*)d_in[3];
    const int*   qw_out = (const int*)  d_in[4];
    const int*   qz_out = (const int*)  d_in[5];
    const float* sc_out = (const float*)d_in[6];
    float* out = (float*)d_out;

    float *WqkvT, *qkv, *WoutT, *ctx, *hs32;
    cudaGetSymbolAddress((void**)&WqkvT, g_WqkvT);
    cudaGetSymbolAddress((void**)&qkv,   g_qkv);
    cudaGetSymbolAddress((void**)&WoutT, g_WoutT);
    cudaGetSymbolAddress((void**)&ctx,   g_ctx);
    cudaGetSymbolAddress((void**)&hs32,  g_hs32);

    cudaFuncSetAttribute(tf32_gemm,
                         cudaFuncAttributeMaxDynamicSharedMemorySize, 3 * STG);
    cudaFuncSetAttribute(attn_mma,
                         cudaFuncAttributeMaxDynamicSharedMemorySize, ATT_SMEM);

    dequant_t_kernel<<<(D_ / 8) * (NQKV / 256), 256>>>(qw_qkv, qz_qkv, sc_qkv, WqkvT, NQKV);
    dequant_t_kernel<<<(D_ / 8) * (D_   / 256), 256>>>(qw_out, qz_out, sc_out, WoutT, D_);
    tf32_copy_kernel<<<(MROWS * (D_ / 4)) / 256, 256>>>((const float4*)hs, (float4*)hs32);

    dim3 g1(NQKV / 256, MROWS / 128);
    tf32_gemm<<<g1, 256, 3 * STG>>>(hs32, WqkvT, qkv, NQKV);

    rope_kernel<<<B_ * S_, 512>>>(qkv);

    // round all of qkv to tf32 so attention ldmatrix feeds exact tf32
    tf32_inplace_kernel<<<(MROWS * (NQKV / 4)) / 256, 256>>>((float4*)qkv);

    dim3 g2(S_ / 64, 32);
    attn_mma<<<g2, 128, ATT_SMEM>>>(qkv, ctx);

    dim3 g3(D_ / 256, MROWS / 128);
    tf32_gemm<<<g3, 256, 3 * STG>>>(ctx, WoutT, out, D_);
}

// round 8
// speedup vs baseline: 1.8964x; 1.0221x over previous
#include <cuda_runtime.h>
#include <cstdint>

#define B_ 2
#define S_ 2048
#define D_ 4096
#define NQKV 12288
#define MROWS 4096

// ---------------- scratch ----------------------------------------------------
__device__ float g_WqkvT[(size_t)NQKV * D_];
__device__ float g_qkv  [(size_t)MROWS * NQKV];
__device__ float g_WoutT[(size_t)D_ * D_];
__device__ float g_ctx  [(size_t)MROWS * D_];
__device__ float g_hs32 [(size_t)MROWS * D_];

__device__ __forceinline__ uint32_t smem_u32(const void* p) {
    uint32_t a;
    asm("{ .reg .u64 t; cvta.to.shared.u64 t, %1; cvt.u32.u64 %0, t; }" : "=r"(a) : "l"(p));
    return a;
}
__device__ __forceinline__ float tf32f(float x) {
    uint32_t r; asm("cvt.rna.tf32.f32 %0, %1;" : "=r"(r) : "f"(x));
    return __uint_as_float(r);
}
__device__ __forceinline__ void ldsm4(uint32_t& r0, uint32_t& r1, uint32_t& r2,
                                      uint32_t& r3, uint32_t addr) {
    asm volatile("ldmatrix.sync.aligned.m8n8.x4.shared.b16 {%0,%1,%2,%3}, [%4];"
                 : "=r"(r0), "=r"(r1), "=r"(r2), "=r"(r3) : "r"(addr));
}
#define CPA16(dst, src) \
    asm volatile("cp.async.cg.shared.global [%0], [%1], 16;" :: "r"(dst), "l"(src))
#define MMA8(d, a, b0_, b1_) \
    asm volatile("mma.sync.aligned.m16n8k8.row.col.f32.tf32.tf32.f32 " \
                 "{%0,%1,%2,%3}, {%4,%5,%6,%7}, {%8,%9}, {%0,%1,%2,%3};" \
                 : "+f"(d[0]), "+f"(d[1]), "+f"(d[2]), "+f"(d[3]) \
                 : "r"(a[0]), "r"(a[1]), "r"(a[2]), "r"(a[3]), "r"(b0_), "r"(b1_))

// ---------------- GPTQ 4-bit dequant -> W^T [N,K], tf32-rounded -------------
__global__ void dequant_t_kernel(const int* __restrict__ qw, const int* __restrict__ qz,
                                 const float* __restrict__ sc, float* __restrict__ Wt, int N) {
    size_t idx = (size_t)blockIdx.x * blockDim.x + threadIdx.x;
    if (idx >= (size_t)(D_ / 8) * N) return;
    int n = (int)(idx % N);
    int r = (int)(idx / N);
    int g = r >> 4;
    unsigned w = (unsigned)qw[(size_t)r * N + n];
    unsigned z = (unsigned)qz[(size_t)g * (N / 8) + (n >> 3)];
    int zp = (int)((z >> ((n & 7) * 4)) & 15u) + 1;
    float s = sc[(size_t)g * N + n];
    float v[8];
#pragma unroll
    for (int j = 0; j < 8; j++)
        v[j] = tf32f(s * (float)((int)((w >> (j * 4)) & 15u) - zp));
    float* dst = Wt + (size_t)n * D_ + (size_t)r * 8;
    *(float4*)dst       = make_float4(v[0], v[1], v[2], v[3]);
    *(float4*)(dst + 4) = make_float4(v[4], v[5], v[6], v[7]);
}

__global__ void tf32_copy_kernel(const float4* __restrict__ src, float4* __restrict__ dst) {
    size_t i = (size_t)blockIdx.x * blockDim.x + threadIdx.x;
    float4 v = src[i];
    dst[i] = make_float4(tf32f(v.x), tf32f(v.y), tf32f(v.z), tf32f(v.w));
}

// ---------------- tf32 mma GEMM v3: 4-stage pipeline + rasterization ---------
// 256 thr, 8 warps (2Mx4N), block 128x256, warp 64x64, BK=32. 1D grid.
#define STG 49152
__global__ __launch_bounds__(256, 1) void tf32_gemm(const float* __restrict__ A,
                                                    const float* __restrict__ Bt,
                                                    float* __restrict__ C, int N,
                                                    int round_out) {
    extern __shared__ char smraw[];
    const uint32_t sb = smem_u32(smraw);
    const int tid = threadIdx.x;
    const int L = tid & 31;
    const int wid = tid >> 5;
    const int wm = wid >> 2, wn = wid & 3;

    // rasterize: groups of 16 by-rows, bx sweeps within group
    const int gx = N >> 8;                 // N/256
    int lin = blockIdx.x;
    int rpg = gx << 4;
    int grp = lin / rpg;
    int rem = lin - grp * rpg;
    int by = (grp << 4) + (rem & 15);
    int bx = rem >> 4;

    const float* Ag = A + (size_t)(by * 128) * 4096;
    const float* Bg = Bt + (size_t)(bx * 256) * 4096;

    auto stage_load = [&](int kc, int st) {
        uint32_t sA = sb + st * STG;
        uint32_t sB = sA + 16384;
        const float* Ap = Ag + kc * 32;
        const float* Bp = Bg + kc * 32;
#pragma unroll
        for (int i = 0; i < 4; i++) {
            int f = tid + i * 256, r = f >> 3, c = f & 7;
            CPA16(sA + r * 128 + ((c * 16) ^ ((r & 7) << 4)), Ap + (size_t)r * 4096 + c * 4);
        }
#pragma unroll
        for (int i = 0; i < 8; i++) {
            int f = tid + i * 256, r = f >> 3, c = f & 7;
            CPA16(sB + r * 128 + ((c * 16) ^ ((r & 7) << 4)), Bp + (size_t)r * 4096 + c * 4);
        }
        asm volatile("cp.async.commit_group;" ::: "memory");
    };

    float acc[4][8][4];
#pragma unroll
    for (int mt = 0; mt < 4; mt++)
#pragma unroll
        for (int nt = 0; nt < 8; nt++)
#pragma unroll
            for (int j = 0; j < 4; j++) acc[mt][nt][j] = 0.f;

    stage_load(0, 0);
    stage_load(1, 1);
    stage_load(2, 2);

#pragma unroll 1
    for (int i = 0; i < 128; i++) {
        if (i <= 125)      asm volatile("cp.async.wait_group 2;" ::: "memory");
        else if (i == 126) asm volatile("cp.async.wait_group 1;" ::: "memory");
        else               asm volatile("cp.async.wait_group 0;" ::: "memory");
        __syncthreads();
        if (i + 3 < 128) stage_load(i + 3, (i + 3) & 3);
        uint32_t sA = sb + (i & 3) * STG;
        uint32_t sB = sA + 16384;
#pragma unroll
        for (int ks = 0; ks < 4; ks++) {
            uint32_t a[4][4];
#pragma unroll
            for (int mt = 0; mt < 4; mt++) {
                int row = wm * 64 + mt * 16 + (L & 15);
                ldsm4(a[mt][0], a[mt][1], a[mt][2], a[mt][3],
                      sA + row * 128 + (((2 * ks + (L >> 4)) * 16) ^ ((row & 7) << 4)));
            }
#pragma unroll
            for (int np = 0; np < 4; np++) {
                int n = wn * 64 + np * 16 + ((L & 7) | ((L & 16) >> 1));
                uint32_t b0, b1, b2, b3;
                ldsm4(b0, b1, b2, b3,
                      sB + n * 128 + (((2 * ks + ((L >> 3) & 1)) * 16) ^ ((n & 7) << 4)));
#pragma unroll
                for (int mt = 0; mt < 4; mt++) {
                    MMA8(acc[mt][2 * np], a[mt], b0, b1);
                    MMA8(acc[mt][2 * np + 1], a[mt], b2, b3);
                }
            }
        }
    }

    const int row0 = by * 128 + wm * 64 + (L >> 2);
    const int col0 = bx * 256 + wn * 64 + 2 * (L & 3);
    if (round_out) {
#pragma unroll
        for (int mt = 0; mt < 4; mt++)
#pragma unroll
            for (int nt = 0; nt < 8; nt++) {
                float* p = C + (size_t)(row0 + mt * 16) * N + col0 + nt * 8;
                *(float2*)p = make_float2(tf32f(acc[mt][nt][0]), tf32f(acc[mt][nt][1]));
                *(float2*)(p + (size_t)8 * N) =
                    make_float2(tf32f(acc[mt][nt][2]), tf32f(acc[mt][nt][3]));
            }
    } else {
#pragma unroll
        for (int mt = 0; mt < 4; mt++)
#pragma unroll
            for (int nt = 0; nt < 8; nt++) {
                float* p = C + (size_t)(row0 + mt * 16) * N + col0 + nt * 8;
                *(float2*)p = make_float2(acc[mt][nt][0], acc[mt][nt][1]);
                *(float2*)(p + (size_t)8 * N) = make_float2(acc[mt][nt][2], acc[mt][nt][3]);
            }
    }
}

// ---------------- RoPE (rounds rotated values back to tf32) ------------------
__global__ void rope_kernel(float* __restrict__ qkv) {
    int bs = blockIdx.x;
    int s = bs & (S_ - 1);
    int h = threadIdx.x >> 5;
    int i = threadIdx.x & 31;
    float inv_freq = 1.0f / powf(10000.0f, (float)(2 * i) / 64.0f);
    float ang = (float)s * inv_freq;
    float sn = sinf(ang), cs = cosf(ang);
    size_t base = (size_t)bs * NQKV + (size_t)h * 256 + 2 * i;
    float* q = qkv + base;
    float* k = qkv + base + D_;
    float q0 = q[0], q1 = q[1];
    q[0] = tf32f(q0 * cs - q1 * sn);
    q[1] = tf32f(q1 * cs + q0 * sn);
    float k0 = k[0], k1 = k[1];
    k[0] = tf32f(k0 * cs - k1 * sn);
    k[1] = tf32f(k1 * cs + k0 * sn);
}

// ---------------- tensor-core causal flash attention (unchanged) -------------
#define ATT_SMEM 204800
__global__ __launch_bounds__(128, 1) void attn_mma(const float* __restrict__ qkv,
                                                   float* __restrict__ ctx) {
    extern __shared__ char smraw[];
    const uint32_t sb = smem_u32(smraw);
    const int tid = threadIdx.x, w = tid >> 5, L = tid & 31;
    const int qb = gridDim.x - 1 - blockIdx.x;
    const int b = blockIdx.y >> 4, h = blockIdx.y & 15;
    const int qg0 = qb * 64;
    const float* base = qkv + (size_t)b * S_ * NQKV;
    const int nkt = 2 * qb + 2;

#pragma unroll
    for (int i = 0; i < 32; i++) {
        int f = tid + i * 128, q = f >> 6, c4 = f & 63;
        CPA16(sb + (q * 8 + (c4 >> 3)) * 128 + (((c4 & 7) * 16) ^ ((q & 7) << 4)),
              base + (size_t)(qg0 + q) * NQKV + h * 256 + c4 * 4);
    }
#pragma unroll
    for (int i = 0; i < 16; i++) {
        int f = tid + i * 128, key = f >> 6, c4 = f & 63;
        CPA16(sb + 65536 + (key * 8 + (c4 >> 3)) * 128 + (((c4 & 7) * 16) ^ ((key & 7) << 4)),
              base + (size_t)key * NQKV + D_ + h * 256 + c4 * 4);
    }
    asm volatile("cp.async.commit_group;" ::: "memory");

    float O[32][4];
#pragma unroll
    for (int nt = 0; nt < 32; nt++)
#pragma unroll
        for (int j = 0; j < 4; j++) O[nt][j] = 0.f;
    float mlo = -1e30f, mhi = -1e30f, llo = 0.f, lhi = 0.f;

#pragma unroll 1
    for (int kt = 0; kt < nkt; kt++) {
        const int k0 = kt * 32, buf = kt & 1;
        const uint32_t Kb = sb + 65536 + buf * 32768;
        const uint32_t Vb = sb + 131072 + buf * 32768;

        const float* vsrc = base + (size_t)(k0 + L) * NQKV + 2 * D_ + h * 256 + 64 * w;
        float4 vreg[8];
#pragma unroll
        for (int j = 0; j < 8; j++) vreg[j] = *(const float4*)(vsrc + 4 * j);

        asm volatile("cp.async.wait_group 0;" ::: "memory");
        __syncthreads();

        if (kt + 1 < nkt) {
            uint32_t Kn = sb + 65536 + (buf ^ 1) * 32768;
#pragma unroll
            for (int i = 0; i < 16; i++) {
                int f = tid + i * 128, key = f >> 6, c4 = f & 63;
                CPA16(Kn + (key * 8 + (c4 >> 3)) * 128 + (((c4 & 7) * 16) ^ ((key & 7) << 4)),
                      base + (size_t)(k0 + 32 + key) * NQKV + D_ + h * 256 + c4 * 4);
            }
            asm volatile("cp.async.commit_group;" ::: "memory");
        }

        float s[4][4];
#pragma unroll
        for (int nt = 0; nt < 4; nt++)
#pragma unroll
            for (int j = 0; j < 4; j++) s[nt][j] = 0.f;

#pragma unroll
        for (int ks = 0; ks < 16; ks++) {
            uint32_t a[4];
            int row = 16 * w + (L & 15);
            ldsm4(a[0], a[1], a[2], a[3],
                  sb + (row * 8 + (ks >> 2)) * 128 +
                  (((2 * (ks & 3) + (L >> 4)) * 16) ^ ((L & 7) << 4)));
#pragma unroll
            for (int np = 0; np < 2; np++) {
                int n = np * 16 + ((L & 7) | ((L & 16) >> 1));
                uint32_t b0, b1, b2, b3;
                ldsm4(b0, b1, b2, b3,
                      Kb + (n * 8 + (ks >> 2)) * 128 +
                      (((2 * (ks & 3) + ((L >> 3) & 1)) * 16) ^ ((n & 7) << 4)));
                MMA8(s[2 * np], a, b0, b1);
                MMA8(s[2 * np + 1], a, b2, b3);
            }
        }
#pragma unroll
        for (int j = 0; j < 8; j++) {
            int d0 = 64 * w + 4 * j;
            float vv[4] = {vreg[j].x, vreg[j].y, vreg[j].z, vreg[j].w};
#pragma unroll
            for (int e = 0; e < 4; e++) {
                int d = d0 + e;
                *(float*)(smraw + 131072 + buf * 32768 + d * 128 +
                          ((4 * L) ^ ((d & 7) << 4))) = vv[e];
            }
        }
#pragma unroll
        for (int j = 0; j < 8; j++) vreg[j] = *(const float4*)(vsrc + 32 + 4 * j);
#pragma unroll
        for (int ks = 16; ks < 32; ks++) {
            uint32_t a[4];
            int row = 16 * w + (L & 15);
            ldsm4(a[0], a[1], a[2], a[3],
                  sb + (row * 8 + (ks >> 2)) * 128 +
                  (((2 * (ks & 3) + (L >> 4)) * 16) ^ ((L & 7) << 4)));
#pragma unroll
            for (int np = 0; np < 2; np++) {
                int n = np * 16 + ((L & 7) | ((L & 16) >> 1));
                uint32_t b0, b1, b2, b3;
                ldsm4(b0, b1, b2, b3,
                      Kb + (n * 8 + (ks >> 2)) * 128 +
                      (((2 * (ks & 3) + ((L >> 3) & 1)) * 16) ^ ((n & 7) << 4)));
                MMA8(s[2 * np], a, b0, b1);
                MMA8(s[2 * np + 1], a, b2, b3);
            }
        }
#pragma unroll
        for (int j = 0; j < 8; j++) {
            int d0 = 64 * w + 32 + 4 * j;
            float vv[4] = {vreg[j].x, vreg[j].y, vreg[j].z, vreg[j].w};
#pragma unroll
            for (int e = 0; e < 4; e++) {
                int d = d0 + e;
                *(float*)(smraw + 131072 + buf * 32768 + d * 128 +
                          ((4 * L) ^ ((d & 7) << 4))) = vv[e];
            }
        }
        __syncthreads();

#pragma unroll
        for (int nt = 0; nt < 4; nt++)
#pragma unroll
            for (int j = 0; j < 4; j++) s[nt][j] *= 0.0625f;
        if (k0 + 31 > qg0 + 16 * w) {
            int glo = qg0 + 16 * w + (L >> 2);
#pragma unroll
            for (int nt = 0; nt < 4; nt++) {
                int col = k0 + nt * 8 + 2 * (L & 3);
                if (col > glo)         s[nt][0] = -1e30f;
                if (col + 1 > glo)     s[nt][1] = -1e30f;
                if (col > glo + 8)     s[nt][2] = -1e30f;
                if (col + 1 > glo + 8) s[nt][3] = -1e30f;
            }
        }
        float tlo = -1e30f, thi = -1e30f;
#pragma unroll
        for (int nt = 0; nt < 4; nt++) {
            tlo = fmaxf(tlo, fmaxf(s[nt][0], s[nt][1]));
            thi = fmaxf(thi, fmaxf(s[nt][2], s[nt][3]));
        }
        tlo = fmaxf(tlo, __shfl_xor_sync(0xffffffffu, tlo, 1));
        tlo = fmaxf(tlo, __shfl_xor_sync(0xffffffffu, tlo, 2));
        thi = fmaxf(thi, __shfl_xor_sync(0xffffffffu, thi, 1));
        thi = fmaxf(thi, __shfl_xor_sync(0xffffffffu, thi, 2));
        float mnl = fmaxf(mlo, tlo), mnh = fmaxf(mhi, thi);
        float rl = __expf(mlo - mnl), rh = __expf(mhi - mnh);
        mlo = mnl; mhi = mnh;
#pragma unroll
        for (int nt = 0; nt < 32; nt++) {
            O[nt][0] *= rl; O[nt][1] *= rl; O[nt][2] *= rh; O[nt][3] *= rh;
        }
        float psl = 0.f, psh = 0.f;
        {
            int qlo = 16 * w + (L >> 2);
            uint32_t swz = ((qlo & 7) << 4);
#pragma unroll
            for (int nt = 0; nt < 4; nt++) {
                float p0 = tf32f(__expf(s[nt][0] - mnl));
                float p1 = tf32f(__expf(s[nt][1] - mnl));
                float p2 = tf32f(__expf(s[nt][2] - mnh));
                float p3 = tf32f(__expf(s[nt][3] - mnh));
                psl += p0 + p1; psh += p2 + p3;
                uint32_t off = (uint32_t)(nt * 32 + 8 * (L & 3));
                *(float2*)(smraw + 196608 + qlo * 128 + (off ^ swz)) = make_float2(p0, p1);
                *(float2*)(smraw + 196608 + (qlo + 8) * 128 + (off ^ swz)) = make_float2(p2, p3);
            }
        }
        psl += __shfl_xor_sync(0xffffffffu, psl, 1);
        psl += __shfl_xor_sync(0xffffffffu, psl, 2);
        psh += __shfl_xor_sync(0xffffffffu, psh, 1);
        psh += __shfl_xor_sync(0xffffffffu, psh, 2);
        llo = llo * rl + psl;
        lhi = lhi * rh + psh;
        __syncwarp();

#pragma unroll
        for (int ks = 0; ks < 4; ks++) {
            uint32_t a[4];
            int row = 16 * w + (L & 15);
            ldsm4(a[0], a[1], a[2], a[3],
                  sb + 196608 + row * 128 + (((2 * ks + (L >> 4)) * 16) ^ ((L & 7) << 4)));
#pragma unroll
            for (int np = 0; np < 16; np++) {
                int d = np * 16 + ((L & 7) | ((L & 16) >> 1));
                uint32_t b0, b1, b2, b3;
                ldsm4(b0, b1, b2, b3,
                      Vb + d * 128 + (((2 * ks + ((L >> 3) & 1)) * 16) ^ ((d & 7) << 4)));
                MMA8(O[2 * np], a, b0, b1);
                MMA8(O[2 * np + 1], a, b2, b3);
            }
        }
        __syncwarp();
    }

    float il = 1.f / llo, ih = 1.f / lhi;
    float* cp = ctx + ((size_t)(b * S_ + qg0 + 16 * w + (L >> 2))) * D_ + h * 256 + 2 * (L & 3);
#pragma unroll
    for (int nt = 0; nt < 32; nt++) {
        *(float2*)(cp + nt * 8) =
            make_float2(tf32f(O[nt][0] * il), tf32f(O[nt][1] * il));
        *(float2*)(cp + (size_t)8 * D_ + nt * 8) =
            make_float2(tf32f(O[nt][2] * ih), tf32f(O[nt][3] * ih));
    }
}

// ---------------- launch ------------------------------------------------------
extern "C" void kernel_launch(void* const* d_in, const int* in_sizes, int n_in,
                              void* d_out, int out_size) {
    const float* hs     = (const float*)d_in[0];
    const int*   qw_qkv = (const int*)  d_in[1];
    const int*   qz_qkv = (const int*)  d_in[2];
    const float* sc_qkv = (const float*)d_in[3];
    const int*   qw_out = (const int*)  d_in[4];
    const int*   qz_out = (const int*)  d_in[5];
    const float* sc_out = (const float*)d_in[6];
    float* out = (float*)d_out;

    float *WqkvT, *qkv, *WoutT, *ctx, *hs32;
    cudaGetSymbolAddress((void**)&WqkvT, g_WqkvT);
    cudaGetSymbolAddress((void**)&qkv,   g_qkv);
    cudaGetSymbolAddress((void**)&WoutT, g_WoutT);
    cudaGetSymbolAddress((void**)&ctx,   g_ctx);
    cudaGetSymbolAddress((void**)&hs32,  g_hs32);

    cudaFuncSetAttribute(tf32_gemm,
                         cudaFuncAttributeMaxDynamicSharedMemorySize, 4 * STG);
    cudaFuncSetAttribute(attn_mma,
                         cudaFuncAttributeMaxDynamicSharedMemorySize, ATT_SMEM);

    dequant_t_kernel<<<(D_ / 8) * (NQKV / 256), 256>>>(qw_qkv, qz_qkv, sc_qkv, WqkvT, NQKV);
    dequant_t_kernel<<<(D_ / 8) * (D_   / 256), 256>>>(qw_out, qz_out, sc_out, WoutT, D_);
    tf32_copy_kernel<<<(MROWS * (D_ / 4)) / 256, 256>>>((const float4*)hs, (float4*)hs32);

    // QKV GEMM: rounds output to tf32 in epilogue (feeds attention mma)
    tf32_gemm<<<(NQKV / 256) * (MROWS / 128), 256, 4 * STG>>>(hs32, WqkvT, qkv, NQKV, 1);

    rope_kernel<<<B_ * S_, 512>>>(qkv);

    attn_mma<<<dim3(S_ / 64, 32), 128, ATT_SMEM>>>(qkv, ctx);

    // out GEMM: plain fp32 output
    tf32_gemm<<<(D_ / 256) * (MROWS / 128), 256, 4 * STG>>>(ctx, WoutT, out, D_, 0);
}

// round 9
// speedup vs baseline: 4.1095x; 2.1670x over previous
#include <cuda_runtime.h>
#include <cuda_fp16.h>
#include <cstdint>

#define B_ 2
#define S_ 2048
#define D_ 4096
#define NQKV 12288
#define MROWS 4096

// ---------------- scratch (fp16 operands) ------------------------------------
__device__ __half g_WqkvT[(size_t)NQKV * D_];   // 96 MB
__device__ __half g_qkv  [(size_t)MROWS * NQKV];// 96 MB
__device__ __half g_WoutT[(size_t)D_ * D_];     // 32 MB
__device__ __half g_ctx  [(size_t)MROWS * D_];  // 32 MB
__device__ __half g_hs16 [(size_t)MROWS * D_];  // 32 MB

__device__ __forceinline__ uint32_t smem_u32(const void* p) {
    uint32_t a;
    asm("{ .reg .u64 t; cvta.to.shared.u64 t, %1; cvt.u32.u64 %0, t; }" : "=r"(a) : "l"(p));
    return a;
}
__device__ __forceinline__ void ldsm4(uint32_t& r0, uint32_t& r1, uint32_t& r2,
                                      uint32_t& r3, uint32_t addr) {
    asm volatile("ldmatrix.sync.aligned.m8n8.x4.shared.b16 {%0,%1,%2,%3}, [%4];"
                 : "=r"(r0), "=r"(r1), "=r"(r2), "=r"(r3) : "r"(addr));
}
__device__ __forceinline__ void ldsm4t(uint32_t& r0, uint32_t& r1, uint32_t& r2,
                                       uint32_t& r3, uint32_t addr) {
    asm volatile("ldmatrix.sync.aligned.m8n8.x4.trans.shared.b16 {%0,%1,%2,%3}, [%4];"
                 : "=r"(r0), "=r"(r1), "=r"(r2), "=r"(r3) : "r"(addr));
}
#define CPA16(dst, src) \
    asm volatile("cp.async.cg.shared.global [%0], [%1], 16;" :: "r"(dst), "l"(src))
#define MMA16(d, a, b0_, b1_) \
    asm volatile("mma.sync.aligned.m16n8k16.row.col.f32.f16.f16.f32 " \
                 "{%0,%1,%2,%3}, {%4,%5,%6,%7}, {%8,%9}, {%0,%1,%2,%3};" \
                 : "+f"(d[0]), "+f"(d[1]), "+f"(d[2]), "+f"(d[3]) \
                 : "r"(a[0]), "r"(a[1]), "r"(a[2]), "r"(a[3]), "r"(b0_), "r"(b1_))

// ---------------- GPTQ 4-bit dequant -> W^T [N,K] fp16 -----------------------
__global__ void dequant_t_kernel(const int* __restrict__ qw, const int* __restrict__ qz,
                                 const float* __restrict__ sc, __half* __restrict__ Wt, int N) {
    size_t idx = (size_t)blockIdx.x * blockDim.x + threadIdx.x;
    if (idx >= (size_t)(D_ / 8) * N) return;
    int n = (int)(idx % N);
    int r = (int)(idx / N);
    int g = r >> 4;
    unsigned w = (unsigned)qw[(size_t)r * N + n];
    unsigned z = (unsigned)qz[(size_t)g * (N / 8) + (n >> 3)];
    int zp = (int)((z >> ((n & 7) * 4)) & 15u) + 1;
    float s = sc[(size_t)g * N + n];
    __half2 h[4];
#pragma unroll
    for (int j = 0; j < 4; j++) {
        float v0 = s * (float)((int)((w >> (j * 8)) & 15u) - zp);
        float v1 = s * (float)((int)((w >> (j * 8 + 4)) & 15u) - zp);
        h[j] = __floats2half2_rn(v0, v1);
    }
    *(uint4*)(Wt + (size_t)n * D_ + (size_t)r * 8) = *(uint4*)h;
}

__global__ void h16_copy_kernel(const float4* __restrict__ src, uint4* __restrict__ dst) {
    size_t i = (size_t)blockIdx.x * blockDim.x + threadIdx.x;
    float4 a = src[2 * i], b = src[2 * i + 1];
    __half2 h[4] = {__floats2half2_rn(a.x, a.y), __floats2half2_rn(a.z, a.w),
                    __floats2half2_rn(b.x, b.y), __floats2half2_rn(b.z, b.w)};
    dst[i] = *(uint4*)h;
}

// ---------------- fp16 mma GEMM: C[M,N] = A[M,K] @ Bt[N,K]^T -----------------
// 256 thr, 8 warps (2Mx4N), block 128x256, warp 64x64, BK=64 halves (128B rows),
// 4-stage cp.async, rasterized 1D grid. K=4096 -> 64 chunks.
#define STG 49152
__global__ __launch_bounds__(256, 1) void fp16_gemm(const __half* __restrict__ A,
                                                    const __half* __restrict__ Bt,
                                                    void* __restrict__ Cv, int N,
                                                    int out_half) {
    extern __shared__ char smraw[];
    const uint32_t sb = smem_u32(smraw);
    const int tid = threadIdx.x;
    const int L = tid & 31;
    const int wid = tid >> 5;
    const int wm = wid >> 2, wn = wid & 3;

    const int gx = N >> 8;
    int rpg = gx << 4;
    int grp = blockIdx.x / rpg;
    int rem = blockIdx.x - grp * rpg;
    int by = (grp << 4) + (rem & 15);
    int bx = rem >> 4;

    const __half* Ag = A + (size_t)(by * 128) * 4096;
    const __half* Bg = Bt + (size_t)(bx * 256) * 4096;

    auto stage_load = [&](int kc, int st) {
        uint32_t sA = sb + st * STG;
        uint32_t sB = sA + 16384;
        const __half* Ap = Ag + kc * 64;
        const __half* Bp = Bg + kc * 64;
#pragma unroll
        for (int i = 0; i < 4; i++) {
            int f = tid + i * 256, r = f >> 3, c = f & 7;
            CPA16(sA + r * 128 + ((c * 16) ^ ((r & 7) << 4)), Ap + (size_t)r * 4096 + c * 8);
        }
#pragma unroll
        for (int i = 0; i < 8; i++) {
            int f = tid + i * 256, r = f >> 3, c = f & 7;
            CPA16(sB + r * 128 + ((c * 16) ^ ((r & 7) << 4)), Bp + (size_t)r * 4096 + c * 8);
        }
        asm volatile("cp.async.commit_group;" ::: "memory");
    };

    float acc[4][8][4];
#pragma unroll
    for (int mt = 0; mt < 4; mt++)
#pragma unroll
        for (int nt = 0; nt < 8; nt++)
#pragma unroll
            for (int j = 0; j < 4; j++) acc[mt][nt][j] = 0.f;

    stage_load(0, 0);
    stage_load(1, 1);
    stage_load(2, 2);

#pragma unroll 1
    for (int i = 0; i < 64; i++) {
        if (i <= 61)      asm volatile("cp.async.wait_group 2;" ::: "memory");
        else if (i == 62) asm volatile("cp.async.wait_group 1;" ::: "memory");
        else              asm volatile("cp.async.wait_group 0;" ::: "memory");
        __syncthreads();
        if (i + 3 < 64) stage_load(i + 3, (i + 3) & 3);
        uint32_t sA = sb + (i & 3) * STG;
        uint32_t sB = sA + 16384;
#pragma unroll
        for (int ks = 0; ks < 4; ks++) {
            uint32_t a[4][4];
#pragma unroll
            for (int mt = 0; mt < 4; mt++) {
                int row = wm * 64 + mt * 16 + (L & 15);
                ldsm4(a[mt][0], a[mt][1], a[mt][2], a[mt][3],
                      sA + row * 128 + (((2 * ks + (L >> 4)) * 16) ^ ((row & 7) << 4)));
            }
#pragma unroll
            for (int np = 0; np < 4; np++) {
                int n = wn * 64 + np * 16 + ((L & 7) | ((L & 16) >> 1));
                uint32_t b0, b1, b2, b3;
                ldsm4(b0, b1, b2, b3,
                      sB + n * 128 + (((2 * ks + ((L >> 3) & 1)) * 16) ^ ((n & 7) << 4)));
#pragma unroll
                for (int mt = 0; mt < 4; mt++) {
                    MMA16(acc[mt][2 * np], a[mt], b0, b1);
                    MMA16(acc[mt][2 * np + 1], a[mt], b2, b3);
                }
            }
        }
    }

    const int row0 = by * 128 + wm * 64 + (L >> 2);
    const int col0 = bx * 256 + wn * 64 + 2 * (L & 3);
    if (out_half) {
        __half* C = (__half*)Cv;
#pragma unroll
        for (int mt = 0; mt < 4; mt++)
#pragma unroll
            for (int nt = 0; nt < 8; nt++) {
                __half* p = C + (size_t)(row0 + mt * 16) * N + col0 + nt * 8;
                *(__half2*)p = __floats2half2_rn(acc[mt][nt][0], acc[mt][nt][1]);
                *(__half2*)(p + (size_t)8 * N) = __floats2half2_rn(acc[mt][nt][2], acc[mt][nt][3]);
            }
    } else {
        float* C = (float*)Cv;
#pragma unroll
        for (int mt = 0; mt < 4; mt++)
#pragma unroll
            for (int nt = 0; nt < 8; nt++) {
                float* p = C + (size_t)(row0 + mt * 16) * N + col0 + nt * 8;
                *(float2*)p = make_float2(acc[mt][nt][0], acc[mt][nt][1]);
                *(float2*)(p + (size_t)8 * N) = make_float2(acc[mt][nt][2], acc[mt][nt][3]);
            }
    }
}

// ---------------- RoPE on fp16 qkv --------------------------------------------
__global__ void rope_kernel(__half* __restrict__ qkv) {
    int bs = blockIdx.x;
    int s = bs & (S_ - 1);
    int h = threadIdx.x >> 5;
    int i = threadIdx.x & 31;
    float inv_freq = 1.0f / powf(10000.0f, (float)(2 * i) / 64.0f);
    float ang = (float)s * inv_freq;
    float sn = sinf(ang), cs = cosf(ang);
    size_t base = (size_t)bs * NQKV + (size_t)h * 256 + 2 * i;
    __half2* q = (__half2*)(qkv + base);
    __half2* k = (__half2*)(qkv + base + D_);
    float2 qf = __half22float2(*q);
    *q = __floats2half2_rn(qf.x * cs - qf.y * sn, qf.y * cs + qf.x * sn);
    float2 kf = __half22float2(*k);
    *k = __floats2half2_rn(kf.x * cs - kf.y * sn, kf.y * cs + kf.x * sn);
}

// ---------------- fp16 tensor-core causal flash attention --------------------
// 128 thr (4 warps x 16 q rows), 64-q blocks, 32-key tiles. V via ldmatrix.trans.
// SMEM: Q 32KB @0 | K 2x16KB @32768 | V 2x16KB @65536 | P 4KB @98304 = 100KB
#define ATT_SMEM 102400
__global__ __launch_bounds__(128, 2) void attn_mma(const __half* __restrict__ qkv,
                                                   __half* __restrict__ ctx) {
    extern __shared__ char smraw[];
    const uint32_t sb = smem_u32(smraw);
    const int tid = threadIdx.x, w = tid >> 5, L = tid & 31;
    const int qb = gridDim.x - 1 - blockIdx.x;
    const int b = blockIdx.y >> 4, h = blockIdx.y & 15;
    const int qg0 = qb * 64;
    const __half* base = qkv + (size_t)b * S_ * NQKV;
    const int nkt = 2 * qb + 2;

    // stage Q (64 q x 512B) + K0 + V0
#pragma unroll
    for (int i = 0; i < 16; i++) {
        int f = tid + i * 128, q = f >> 5, dc = f & 31;
        int row = q * 4 + (dc >> 3);
        CPA16(sb + row * 128 + (((dc & 7) * 16) ^ ((q & 7) << 4)),
              base + (size_t)(qg0 + q) * NQKV + h * 256 + dc * 8);
    }
#pragma unroll
    for (int i = 0; i < 8; i++) {
        int f = tid + i * 128, key = f >> 5, dc = f & 31;
        int row = key * 4 + (dc >> 3);
        uint32_t off = row * 128 + (((dc & 7) * 16) ^ ((key & 7) << 4));
        const __half* src = base + (size_t)key * NQKV + D_ + h * 256 + dc * 8;
        CPA16(sb + 32768 + off, src);
        CPA16(sb + 65536 + off, src + D_);
    }
    asm volatile("cp.async.commit_group;" ::: "memory");

    float O[32][4];
#pragma unroll
    for (int nt = 0; nt < 32; nt++)
#pragma unroll
        for (int j = 0; j < 4; j++) O[nt][j] = 0.f;
    float mlo = -1e30f, mhi = -1e30f, llo = 0.f, lhi = 0.f;

#pragma unroll 1
    for (int kt = 0; kt < nkt; kt++) {
        const int k0 = kt * 32, buf = kt & 1;
        const uint32_t Kb = sb + 32768 + buf * 16384;
        const uint32_t Vb = sb + 65536 + buf * 16384;

        asm volatile("cp.async.wait_group 0;" ::: "memory");
        __syncthreads();

        if (kt + 1 < nkt) {
            uint32_t Kn = sb + 32768 + (buf ^ 1) * 16384;
            uint32_t Vn = sb + 65536 + (buf ^ 1) * 16384;
#pragma unroll
            for (int i = 0; i < 8; i++) {
                int f = tid + i * 128, key = f >> 5, dc = f & 31;
                int row = key * 4 + (dc >> 3);
                uint32_t off = row * 128 + (((dc & 7) * 16) ^ ((key & 7) << 4));
                const __half* src = base + (size_t)(k0 + 32 + key) * NQKV + D_ + h * 256 + dc * 8;
                CPA16(Kn + off, src);
                CPA16(Vn + off, src + D_);
            }
            asm volatile("cp.async.commit_group;" ::: "memory");
        }

        // ---- S = Q K^T (16 ks of k=16 halves) ----
        float s[4][4];
#pragma unroll
        for (int nt = 0; nt < 4; nt++)
#pragma unroll
            for (int j = 0; j < 4; j++) s[nt][j] = 0.f;
#pragma unroll
        for (int ks = 0; ks < 16; ks++) {
            uint32_t a[4];
            int q = 16 * w + (L & 15);
            ldsm4(a[0], a[1], a[2], a[3],
                  sb + (q * 4 + (ks >> 2)) * 128 +
                  (((2 * (ks & 3) + (L >> 4)) * 16) ^ ((q & 7) << 4)));
#pragma unroll
            for (int np = 0; np < 2; np++) {
                int n = np * 16 + ((L & 7) | ((L & 16) >> 1));
                uint32_t b0, b1, b2, b3;
                ldsm4(b0, b1, b2, b3,
                      Kb + (n * 4 + (ks >> 2)) * 128 +
                      (((2 * (ks & 3) + ((L >> 3) & 1)) * 16) ^ ((n & 7) << 4)));
                MMA16(s[2 * np], a, b0, b1);
                MMA16(s[2 * np + 1], a, b2, b3);
            }
        }

        // ---- online softmax ----
#pragma unroll
        for (int nt = 0; nt < 4; nt++)
#pragma unroll
            for (int j = 0; j < 4; j++) s[nt][j] *= 0.0625f;
        if (k0 + 31 > qg0 + 16 * w) {
            int glo = qg0 + 16 * w + (L >> 2);
#pragma unroll
            for (int nt = 0; nt < 4; nt++) {
                int col = k0 + nt * 8 + 2 * (L & 3);
                if (col > glo)         s[nt][0] = -1e30f;
                if (col + 1 > glo)     s[nt][1] = -1e30f;
                if (col > glo + 8)     s[nt][2] = -1e30f;
                if (col + 1 > glo + 8) s[nt][3] = -1e30f;
            }
        }
        float tlo = -1e30f, thi = -1e30f;
#pragma unroll
        for (int nt = 0; nt < 4; nt++) {
            tlo = fmaxf(tlo, fmaxf(s[nt][0], s[nt][1]));
            thi = fmaxf(thi, fmaxf(s[nt][2], s[nt][3]));
        }
        tlo = fmaxf(tlo, __shfl_xor_sync(0xffffffffu, tlo, 1));
        tlo = fmaxf(tlo, __shfl_xor_sync(0xffffffffu, tlo, 2));
        thi = fmaxf(thi, __shfl_xor_sync(0xffffffffu, thi, 1));
        thi = fmaxf(thi, __shfl_xor_sync(0xffffffffu, thi, 2));
        float mnl = fmaxf(mlo, tlo), mnh = fmaxf(mhi, thi);
        float rl = __expf(mlo - mnl), rh = __expf(mhi - mnh);
        mlo = mnl; mhi = mnh;
#pragma unroll
        for (int nt = 0; nt < 32; nt++) {
            O[nt][0] *= rl; O[nt][1] *= rl; O[nt][2] *= rh; O[nt][3] *= rh;
        }
        float psl = 0.f, psh = 0.f;
        {
            int qlo = 16 * w + (L >> 2);
            int qhi = qlo + 8;
#pragma unroll
            for (int nt = 0; nt < 4; nt++) {
                float p0 = __expf(s[nt][0] - mnl);
                float p1 = __expf(s[nt][1] - mnl);
                float p2 = __expf(s[nt][2] - mnh);
                float p3 = __expf(s[nt][3] - mnh);
                psl += p0 + p1; psh += p2 + p3;
                uint32_t cb = (uint32_t)(nt * 16 + 4 * (L & 3));
                *(__half2*)(smraw + 98304 + (qlo >> 1) * 128 + (qlo & 1) * 64 +
                            (cb ^ (((qlo >> 1) & 3) << 4))) = __floats2half2_rn(p0, p1);
                *(__half2*)(smraw + 98304 + (qhi >> 1) * 128 + (qhi & 1) * 64 +
                            (cb ^ (((qhi >> 1) & 3) << 4))) = __floats2half2_rn(p2, p3);
            }
        }
        psl += __shfl_xor_sync(0xffffffffu, psl, 1);
        psl += __shfl_xor_sync(0xffffffffu, psl, 2);
        psh += __shfl_xor_sync(0xffffffffu, psh, 1);
        psh += __shfl_xor_sync(0xffffffffu, psh, 2);
        llo = llo * rl + psl;
        lhi = lhi * rh + psh;
        __syncwarp();

        // ---- O += P @ V  (V transposed by ldmatrix.trans) ----
#pragma unroll
        for (int ks2 = 0; ks2 < 2; ks2++) {
            uint32_t a[4];
            int q = 16 * w + (L & 15);
            ldsm4(a[0], a[1], a[2], a[3],
                  sb + 98304 + (q >> 1) * 128 + (q & 1) * 64 +
                  ((uint32_t)((2 * ks2 + (L >> 4)) * 16) ^ (((q >> 1) & 3) << 4)));
#pragma unroll
            for (int np = 0; np < 16; np++) {
                int key = ks2 * 16 + (L & 15);
                int dchunk = np * 2 + (L >> 4);
                uint32_t m0, m1, m2, m3;
                ldsm4t(m0, m1, m2, m3,
                       Vb + (key * 4 + (dchunk >> 3)) * 128 +
                       (((dchunk & 7) * 16) ^ ((key & 7) << 4)));
                MMA16(O[2 * np], a, m0, m1);
                MMA16(O[2 * np + 1], a, m2, m3);
            }
        }
        __syncwarp();
    }

    float il = 1.f / llo, ih = 1.f / lhi;
    __half* cp = ctx + ((size_t)(b * S_ + qg0 + 16 * w + (L >> 2))) * D_ + h * 256 + 2 * (L & 3);
#pragma unroll
    for (int nt = 0; nt < 32; nt++) {
        *(__half2*)(cp + nt * 8) = __floats2half2_rn(O[nt][0] * il, O[nt][1] * il);
        *(__half2*)(cp + (size_t)8 * D_ + nt * 8) = __floats2half2_rn(O[nt][2] * ih, O[nt][3] * ih);
    }
}

// ---------------- launch ------------------------------------------------------
extern "C" void kernel_launch(void* const* d_in, const int* in_sizes, int n_in,
                              void* d_out, int out_size) {
    const float* hs     = (const float*)d_in[0];
    const int*   qw_qkv = (const int*)  d_in[1];
    const int*   qz_qkv = (const int*)  d_in[2];
    const float* sc_qkv = (const float*)d_in[3];
    const int*   qw_out = (const int*)  d_in[4];
    const int*   qz_out = (const int*)  d_in[5];
    const float* sc_out = (const float*)d_in[6];
    float* out = (float*)d_out;

    __half *WqkvT, *qkv, *WoutT, *ctx, *hs16;
    cudaGetSymbolAddress((void**)&WqkvT, g_WqkvT);
    cudaGetSymbolAddress((void**)&qkv,   g_qkv);
    cudaGetSymbolAddress((void**)&WoutT, g_WoutT);
    cudaGetSymbolAddress((void**)&ctx,   g_ctx);
    cudaGetSymbolAddress((void**)&hs16,  g_hs16);

    cudaFuncSetAttribute(fp16_gemm,
                         cudaFuncAttributeMaxDynamicSharedMemorySize, 4 * STG);
    cudaFuncSetAttribute(attn_mma,
                         cudaFuncAttributeMaxDynamicSharedMemorySize, ATT_SMEM);

    dequant_t_kernel<<<(D_ / 8) * (NQKV / 256), 256>>>(qw_qkv, qz_qkv, sc_qkv, WqkvT, NQKV);
    dequant_t_kernel<<<(D_ / 8) * (D_   / 256), 256>>>(qw_out, qz_out, sc_out, WoutT, D_);
    h16_copy_kernel<<<(MROWS * (D_ / 8)) / 256, 256>>>((const float4*)hs, (uint4*)hs16);

    // QKV GEMM (fp16 in, fp16 out)
    fp16_gemm<<<(NQKV / 256) * (MROWS / 128), 256, 4 * STG>>>(hs16, WqkvT, qkv, NQKV, 1);

    rope_kernel<<<B_ * S_, 512>>>(qkv);

    attn_mma<<<dim3(S_ / 64, 32), 128, ATT_SMEM>>>(qkv, ctx);

    // out GEMM (fp16 in, fp32 out)
    fp16_gemm<<<(D_ / 256) * (MROWS / 128), 256, 4 * STG>>>(ctx, WoutT, out, D_, 0);
}